// round 15
// baseline (speedup 1.0000x reference)
#include <cuda_runtime.h>
#include <cuda_fp16.h>
#include <cstdint>

#define BATCH 256
#define CCH   256
#define LSQ   512
#define TWOC  512
#define KTOT  512       // [xh ; gathered xh]

// ---------------------------------------------------------------------------
__device__ __half  g_A[CCH * KTOT];                     // 256 KB = fp16(W)
__device__ __half  g_xh[(size_t)BATCH * LSQ * CCH];     // 67 MB [b, l, c]

// ---------------------------------------------------------------------------
__device__ __forceinline__ uint32_t s2u(const void* p) {
    uint32_t a;
    asm("{ .reg .u64 t; cvta.to.shared.u64 t, %1; cvt.u32.u64 %0, t; }" : "=r"(a) : "l"(p));
    return a;
}
__device__ __forceinline__ void cpasync16(uint32_t dst, const void* src) {
    asm volatile("cp.async.cg.shared.global [%0], [%1], 16;" :: "r"(dst), "l"(src) : "memory");
}
__device__ __forceinline__ void cpasync16z(uint32_t dst, const void* src, uint32_t sz) {
    asm volatile("cp.async.cg.shared.global [%0], [%1], 16, %2;"
                 :: "r"(dst), "l"(src), "r"(sz) : "memory");
}
__device__ __forceinline__ void cp_commit() {
    asm volatile("cp.async.commit_group;" ::: "memory");
}
__device__ __forceinline__ void cp_wait1() {
    asm volatile("cp.async.wait_group 1;" ::: "memory");
}
__device__ __forceinline__ void ldm_x4(uint32_t* r, uint32_t addr) {
    asm volatile("ldmatrix.sync.aligned.m8n8.x4.shared.b16 {%0,%1,%2,%3}, [%4];"
                 : "=r"(r[0]), "=r"(r[1]), "=r"(r[2]), "=r"(r[3]) : "r"(addr));
}
__device__ __forceinline__ void mma_f16(float* c, const uint32_t* a, uint32_t b0, uint32_t b1) {
    asm volatile(
        "mma.sync.aligned.m16n8k16.row.col.f32.f16.f16.f32 "
        "{%0,%1,%2,%3}, {%4,%5,%6,%7}, {%8,%9}, {%0,%1,%2,%3};"
        : "+f"(c[0]), "+f"(c[1]), "+f"(c[2]), "+f"(c[3])
        : "r"(a[0]), "r"(a[1]), "r"(a[2]), "r"(a[3]), "r"(b0), "r"(b1));
}

// ---------------------------------------------------------------------------
// Kernel 1: transpose + convert x -> xh[b,l,c] fp16; extra x-slice converts W
// ---------------------------------------------------------------------------
__global__ __launch_bounds__(256)
void conv_kernel(const float* __restrict__ x, const float* __restrict__ W) {
    if (blockIdx.x == 16) {     // prep slice: 512 blocks x 256 threads = 131072 = C*2C
        int i = (blockIdx.z * 2 + blockIdx.y) * 256 + threadIdx.x;
        g_A[i] = __float2half(W[i]);
        return;
    }
    __shared__ float tile[128][33];
    int b  = blockIdx.z;
    int l0 = blockIdx.x * 32;
    int c0 = blockIdx.y * 128;
    int lane = threadIdx.x & 31, w = threadIdx.x >> 5;

    const float* xb = x + ((size_t)b * CCH + c0) * LSQ + l0;
#pragma unroll
    for (int i = 0; i < 16; i++) {
        int c = w + i * 8;
        tile[c][lane] = xb[(size_t)c * LSQ + lane];
    }
    __syncthreads();

#pragma unroll
    for (int i = 0; i < 4; i++) {
        int l = w + i * 8;
        int c4 = lane * 4;
        __half2 h01 = __floats2half2_rn(tile[c4 + 0][l], tile[c4 + 1][l]);
        __half2 h23 = __floats2half2_rn(tile[c4 + 2][l], tile[c4 + 3][l]);
        size_t o = ((size_t)b * LSQ + l0 + l) * CCH + c0 + c4;
        *(uint2*)(g_xh + o) = make_uint2(*(uint32_t*)&h01, *(uint32_t*)&h23);
    }
}

// ---------------------------------------------------------------------------
// Kernel 2: PERSISTENT fused GEMM (K=512, gather in B loads) + InstanceNorm + ReLU
//   item = (b, mt): M=64 channels x N=512, BK=32, 3-stage continuous cp.async
//   512 threads, warps 2(m) x 8(n), one __syncthreads per k-tile.
// ---------------------------------------------------------------------------
#define BK      32
#define STRIDE  80
#define A_SZ    (64 * STRIDE)              // 5120
#define B_SZ    (512 * STRIDE)             // 40960
#define STAGE_B (A_SZ + B_SZ)              // 46080
#define NKT     (KTOT / BK)                // 16
#define NTILES  (4 * BATCH)                // 1024
#define SM_PS   (3 * STAGE_B)              // 138240
#define SM_IDX  (SM_PS + 2 * 64 * 8 * 4)   // 142336
#define GSMEM   (SM_IDX + LSQ * 4)         // 144384

__global__ __launch_bounds__(512, 1)
void gemm_kernel(const int* __restrict__ idx, float* __restrict__ out) {
    extern __shared__ char smem[];
    const uint32_t sb = s2u(smem);
    float* sps  = (float*)(smem + SM_PS);        // [64][8]
    float* sps2 = sps + 64 * 8;                  // [64][8]
    int*   sidx = (int*)(smem + SM_IDX);         // [512]

    const int tid = threadIdx.x;
    const int wid = tid >> 5;
    const int lane = tid & 31;
    const int warp_m = wid & 1;
    const int warp_n = wid >> 1;
    const int grp = lane >> 2, quad = lane & 3;

    const uint32_t a_lm = (uint32_t)(warp_m * 32 + (lane & 15)) * STRIDE + ((lane >> 4) * 16);
    const uint32_t b_lm = (uint32_t)(warp_n * 64 + (lane & 7) + ((lane >> 4) << 3)) * STRIDE
                        + (((lane >> 3) & 1) * 16);

    const int nct = gridDim.x;
    const int my_first = blockIdx.x;
    const int nmy = (my_first < NTILES) ? ((NTILES - 1 - my_first) / nct + 1) : 0;
    if (nmy == 0) return;

    // per-thread load coords
    const int a_row = tid >> 2, a_c16 = tid & 3;          // A: 64x4 chunks (tid<256)

    // load cursor
    int load_item = my_first, load_kt = 0, load_s = 0;
    auto issue = [&]() {
        if (load_item < NTILES) {
            const int mt = load_item & 3, b = load_item >> 2;
            const uint32_t base = sb + load_s * STAGE_B;
            if (tid < 256) {
                const void* src = g_A + (size_t)(mt * 64 + a_row) * KTOT
                                + load_kt * BK + a_c16 * 8;
                cpasync16(base + a_row * STRIDE + a_c16 * 16, src);
            }
            if (load_kt < 8) {          // direct B rows
#pragma unroll
                for (int i = 0; i < 4; i++) {
                    int t = tid + i * 512;
                    int row = t >> 2, c16 = t & 3;
                    const void* src = g_xh + ((size_t)b * LSQ + row) * CCH
                                    + load_kt * BK + c16 * 8;
                    cpasync16(base + A_SZ + row * STRIDE + c16 * 16, src);
                }
            } else {                     // gathered B rows
                const int kb = (load_kt - 8) * BK;
#pragma unroll
                for (int i = 0; i < 4; i++) {
                    int t = tid + i * 512;
                    int row = t >> 2, c16 = t & 3;
                    int j = sidx[row];
                    int jc = (j < LSQ) ? j : 0;
                    uint32_t sz = (j < LSQ) ? 16u : 0u;
                    const void* src = g_xh + ((size_t)b * LSQ + jc) * CCH + kb + c16 * 8;
                    cpasync16z(base + A_SZ + row * STRIDE + c16 * 16, src, sz);
                }
            }
        }
        cp_commit();
        load_s = (load_s == 2) ? 0 : load_s + 1;
        if (++load_kt == NKT) { load_kt = 0; load_item += nct; }
    };

    // prologue: sidx for first item, then 2 stages in flight
    sidx[tid] = idx[(size_t)(my_first >> 2) * LSQ + tid];
    __syncthreads();
    issue();
    issue();

    int comp_s = 0;
    const float inv_l = 1.0f / (float)LSQ;

    for (int it = 0; it < nmy; it++) {
        const int item = my_first + it * nct;
        const int mt = item & 3, b = item >> 2;

        float acc[2][8][4];
#pragma unroll
        for (int i = 0; i < 2; i++)
#pragma unroll
            for (int j = 0; j < 8; j++)
#pragma unroll
                for (int k = 0; k < 4; k++) acc[i][j][k] = 0.f;

#pragma unroll 1
        for (int kt = 0; kt < NKT; kt++) {
            cp_wait1();
            __syncthreads();     // also orders: prev-iter ldmatrix done before overwrite
            issue();

            const uint32_t abase = sb + comp_s * STAGE_B + a_lm;
            const uint32_t bbase = sb + comp_s * STAGE_B + A_SZ + b_lm;
#pragma unroll
            for (int k16 = 0; k16 < 2; k16++) {
                uint32_t af[2][4], bf[4][4];
#pragma unroll
                for (int mi = 0; mi < 2; mi++)
                    ldm_x4(af[mi], abase + mi * 16 * STRIDE + k16 * 32);
#pragma unroll
                for (int bi = 0; bi < 4; bi++)
                    ldm_x4(bf[bi], bbase + bi * 16 * STRIDE + k16 * 32);
#pragma unroll
                for (int mi = 0; mi < 2; mi++)
#pragma unroll
                    for (int ni = 0; ni < 8; ni++)
                        mma_f16(acc[mi][ni], af[mi],
                                bf[ni >> 1][(ni & 1) * 2], bf[ni >> 1][(ni & 1) * 2 + 1]);
            }
            comp_s = (comp_s == 2) ? 0 : comp_s + 1;
        }

        // ---------------- register epilogue (stage buffers stay live) --------
        float ps[2][2]   = {{0.f, 0.f}, {0.f, 0.f}};
        float ps2v[2][2] = {{0.f, 0.f}, {0.f, 0.f}};
#pragma unroll
        for (int mi = 0; mi < 2; mi++)
#pragma unroll
            for (int ni = 0; ni < 8; ni++) {
                float a0 = acc[mi][ni][0], a1 = acc[mi][ni][1];
                float a2 = acc[mi][ni][2], a3 = acc[mi][ni][3];
                ps[mi][0] += a0 + a1;  ps2v[mi][0] += a0 * a0 + a1 * a1;
                ps[mi][1] += a2 + a3;  ps2v[mi][1] += a2 * a2 + a3 * a3;
            }
#pragma unroll
        for (int o = 1; o <= 2; o <<= 1)
#pragma unroll
            for (int mi = 0; mi < 2; mi++)
#pragma unroll
                for (int h = 0; h < 2; h++) {
                    ps[mi][h]   += __shfl_xor_sync(0xffffffffu, ps[mi][h],   o);
                    ps2v[mi][h] += __shfl_xor_sync(0xffffffffu, ps2v[mi][h], o);
                }
        if (quad == 0) {
#pragma unroll
            for (int mi = 0; mi < 2; mi++)
#pragma unroll
                for (int h = 0; h < 2; h++) {
                    int r = warp_m * 32 + mi * 16 + grp + h * 8;
                    sps[r * 8 + warp_n]  = ps[mi][h];
                    sps2[r * 8 + warp_n] = ps2v[mi][h];
                }
        }
        __syncthreads();

#pragma unroll
        for (int mi = 0; mi < 2; mi++) {
#pragma unroll
            for (int h = 0; h < 2; h++) {
                const int r = warp_m * 32 + mi * 16 + grp + h * 8;
                float S = 0.f, S2 = 0.f;
#pragma unroll
                for (int w = 0; w < 8; w++) { S += sps[r * 8 + w]; S2 += sps2[r * 8 + w]; }
                const float mu = S * inv_l;
                const float var = S2 * inv_l - mu * mu;
                const float rstd = rsqrtf(var + 1e-5f);
                float* orow = out + ((size_t)b * CCH + mt * 64 + r) * LSQ;
#pragma unroll
                for (int ni = 0; ni < 8; ni++) {
                    const int col = warp_n * 64 + ni * 8 + quad * 2;
                    float y0 = fmaxf((acc[mi][ni][2 * h + 0] - mu) * rstd, 0.f);
                    float y1 = fmaxf((acc[mi][ni][2 * h + 1] - mu) * rstd, 0.f);
                    *(float2*)&orow[col] = make_float2(y0, y1);
                }
            }
        }

        // sidx for next item (readers of old sidx finished at compute kt=13)
        if (it + 1 < nmy) {
            const int nb = (my_first + (it + 1) * nct) >> 2;
            __syncthreads();                       // out-reads of sps done; safe to reuse path
            sidx[tid] = idx[(size_t)nb * LSQ + tid];
        }
    }
}

// ---------------------------------------------------------------------------
// launch
// ---------------------------------------------------------------------------
extern "C" void kernel_launch(void* const* d_in, const int* in_sizes, int n_in,
                              void* d_out, int out_size) {
    const float* x   = (const float*)d_in[0];   // [B, C, L]
    const int*   idx = (const int*)d_in[1];     // [B, L]
    const float* W   = (const float*)d_in[2];   // [C, 2C] (bias cancels under InstanceNorm)
    float* out = (float*)d_out;

    static int sms = 0;
    if (sms == 0) {
        if (cudaDeviceGetAttribute(&sms, cudaDevAttrMultiProcessorCount, 0) != cudaSuccess
            || sms <= 0)
            sms = 148;
    }

    cudaFuncSetAttribute(gemm_kernel, cudaFuncAttributeMaxDynamicSharedMemorySize, GSMEM);

    dim3 cgrid(17, 2, BATCH);    // x=16 transpose tiles + 1 prep slice
    conv_kernel<<<cgrid, 256>>>(x, W);

    gemm_kernel<<<sms, 512, GSMEM>>>(idx, out);
}

// round 16
// speedup vs baseline: 1.0516x; 1.0516x over previous
#include <cuda_runtime.h>
#include <cuda_fp16.h>
#include <cstdint>

#define BATCH 256
#define CCH   256
#define LSQ   512
#define TWOC  512
#define KTOT  512       // [xh ; gathered xh]

// ---------------------------------------------------------------------------
__device__ __half  g_A[CCH * KTOT];                     // 256 KB  = fp16(W)
__device__ __half  g_xh[(size_t)BATCH * LSQ * CCH];     // 67 MB [b, l, c]

// ---------------------------------------------------------------------------
__device__ __forceinline__ uint32_t s2u(const void* p) {
    uint32_t a;
    asm("{ .reg .u64 t; cvta.to.shared.u64 t, %1; cvt.u32.u64 %0, t; }" : "=r"(a) : "l"(p));
    return a;
}
__device__ __forceinline__ void cpasync16(uint32_t dst, const void* src) {
    asm volatile("cp.async.cg.shared.global [%0], [%1], 16;" :: "r"(dst), "l"(src) : "memory");
}
__device__ __forceinline__ void cpasync16z(uint32_t dst, const void* src, uint32_t sz) {
    asm volatile("cp.async.cg.shared.global [%0], [%1], 16, %2;"
                 :: "r"(dst), "l"(src), "r"(sz) : "memory");
}
__device__ __forceinline__ void cp_commit() {
    asm volatile("cp.async.commit_group;" ::: "memory");
}
__device__ __forceinline__ void cp_wait1() {
    asm volatile("cp.async.wait_group 1;" ::: "memory");
}
__device__ __forceinline__ void cp_wait0() {
    asm volatile("cp.async.wait_group 0;" ::: "memory");
}
__device__ __forceinline__ void ldm_x4(uint32_t* r, uint32_t addr) {
    asm volatile("ldmatrix.sync.aligned.m8n8.x4.shared.b16 {%0,%1,%2,%3}, [%4];"
                 : "=r"(r[0]), "=r"(r[1]), "=r"(r[2]), "=r"(r[3]) : "r"(addr));
}
__device__ __forceinline__ void mma_f16(float* c, const uint32_t* a, uint32_t b0, uint32_t b1) {
    asm volatile(
        "mma.sync.aligned.m16n8k16.row.col.f32.f16.f16.f32 "
        "{%0,%1,%2,%3}, {%4,%5,%6,%7}, {%8,%9}, {%0,%1,%2,%3};"
        : "+f"(c[0]), "+f"(c[1]), "+f"(c[2]), "+f"(c[3])
        : "r"(a[0]), "r"(a[1]), "r"(a[2]), "r"(a[3]), "r"(b0), "r"(b1));
}

// ---------------------------------------------------------------------------
// Kernel 1: A = fp16(W)  (W is [C, 2C] row-major == [M=256, K=512])
// ---------------------------------------------------------------------------
__global__ void prep_kernel(const float* __restrict__ W) {
    int i = blockIdx.x * blockDim.x + threadIdx.x;
    if (i < CCH * KTOT) g_A[i] = __float2half(W[i]);
}

// ---------------------------------------------------------------------------
// Kernel 2: transpose + convert x[b,c,l] f32 -> xh[b,l,c] fp16
// ---------------------------------------------------------------------------
__global__ __launch_bounds__(256)
void conv_kernel(const float* __restrict__ x) {
    __shared__ float tile[128][33];
    int b  = blockIdx.z;
    int l0 = blockIdx.x * 32;
    int c0 = blockIdx.y * 128;
    int lane = threadIdx.x & 31, w = threadIdx.x >> 5;

    const float* xb = x + ((size_t)b * CCH + c0) * LSQ + l0;
#pragma unroll
    for (int i = 0; i < 16; i++) {
        int c = w + i * 8;
        tile[c][lane] = xb[(size_t)c * LSQ + lane];
    }
    __syncthreads();

#pragma unroll
    for (int i = 0; i < 4; i++) {
        int l = w + i * 8;
        int c4 = lane * 4;
        __half2 h01 = __floats2half2_rn(tile[c4 + 0][l], tile[c4 + 1][l]);
        __half2 h23 = __floats2half2_rn(tile[c4 + 2][l], tile[c4 + 3][l]);
        size_t o = ((size_t)b * LSQ + l0 + l) * CCH + c0 + c4;
        *(uint2*)(g_xh + o) = make_uint2(*(uint32_t*)&h01, *(uint32_t*)&h23);
    }
}

// ---------------------------------------------------------------------------
// Kernel 3: fused GEMM (K=512, gather folded into B loads) + InstanceNorm + ReLU
//   CTA: M=64 channels x N=512 (all L), BK=64, 2-stage cp.async
//   512 threads, warp grid 2(m) x 8(n), warp tile 32x64
//   Inner loop: register fragments double-buffered across k16 steps (LDSM
//   latency hidden behind MMA issue).
// ---------------------------------------------------------------------------
#define BK      64
#define STRIDE  144
#define A_SZ    (64 * STRIDE)            // 9216
#define B_SZ    (512 * STRIDE)           // 73728
#define STAGE_B (A_SZ + B_SZ)            // 82944
#define NKT     (KTOT / BK)              // 8
#define SM_IDX  (2 * STAGE_B)            // 165888
#define GSMEM   (SM_IDX + LSQ * 4)       // 167936

__global__ __launch_bounds__(512, 1)
void gemm_kernel(const int* __restrict__ idx, float* __restrict__ out) {
    extern __shared__ char smem[];
    const uint32_t sb = s2u(smem);
    int* sidx = (int*)(smem + SM_IDX);

    const int tid = threadIdx.x;
    const int wid = tid >> 5;
    const int lane = tid & 31;
    const int mt = blockIdx.x;           // 0..3  (64 channels each)
    const int b  = blockIdx.y;

    const int warp_m = wid & 1;          // 32 rows
    const int warp_n = wid >> 1;         // 64 cols
    const int grp = lane >> 2, quad = lane & 3;

    const uint32_t a_lm = (uint32_t)(warp_m * 32 + (lane & 15)) * STRIDE + ((lane >> 4) * 16);
    const uint32_t b_lm = (uint32_t)(warp_n * 64 + (lane & 7) + ((lane >> 4) << 3)) * STRIDE
                        + (((lane >> 3) & 1) * 16);

    sidx[tid] = idx[(size_t)b * LSQ + tid];

    float acc[2][8][4];
#pragma unroll
    for (int i = 0; i < 2; i++)
#pragma unroll
        for (int j = 0; j < 8; j++)
#pragma unroll
            for (int k = 0; k < 4; k++) acc[i][j][k] = 0.f;

    auto load_tile = [&](int kt, int s) {
        const uint32_t base = sb + s * STAGE_B;
        {   // A: 64 rows x 8 chunks = 512 -> one per thread
            int row = tid >> 3, c16 = tid & 7;
            const void* src = g_A + (size_t)(mt * 64 + row) * KTOT + kt * BK + c16 * 8;
            cpasync16(base + row * STRIDE + c16 * 16, src);
        }
        if (kt < 4) {   // direct B rows
#pragma unroll
            for (int i = 0; i < 8; i++) {
                int t = tid + i * 512;
                int row = t >> 3, c16 = t & 7;
                const void* src = g_xh + ((size_t)b * LSQ + row) * CCH + kt * BK + c16 * 8;
                cpasync16(base + A_SZ + row * STRIDE + c16 * 16, src);
            }
        } else {        // gathered B rows (idx indirection; zero-fill pad)
            const int kb = (kt - 4) * BK;
#pragma unroll
            for (int i = 0; i < 8; i++) {
                int t = tid + i * 512;
                int row = t >> 3, c16 = t & 7;
                int j = sidx[row];
                int jc = (j < LSQ) ? j : 0;
                uint32_t sz = (j < LSQ) ? 16u : 0u;
                const void* src = g_xh + ((size_t)b * LSQ + jc) * CCH + kb + c16 * 8;
                cpasync16z(base + A_SZ + row * STRIDE + c16 * 16, src, sz);
            }
        }
        cp_commit();
    };

    __syncthreads();                      // publish sidx
    load_tile(0, 0);
    load_tile(1, 1);

    uint32_t af[2][2][4], bf[2][4][4];    // [buf][frag][regs]

    for (int kt = 0; kt < NKT; kt++) {
        const int s = kt & 1;
        if (kt == NKT - 1) cp_wait0(); else cp_wait1();
        __syncthreads();

        const uint32_t abase = sb + s * STAGE_B + a_lm;
        const uint32_t bbase = sb + s * STAGE_B + A_SZ + b_lm;

        // prefetch k16 = 0 into buf 0
#pragma unroll
        for (int mi = 0; mi < 2; mi++) ldm_x4(af[0][mi], abase + mi * 16 * STRIDE);
#pragma unroll
        for (int bi = 0; bi < 4; bi++) ldm_x4(bf[0][bi], bbase + bi * 16 * STRIDE);

#pragma unroll
        for (int k16 = 0; k16 < 4; k16++) {
            const int cur = k16 & 1;
            const int nxt = cur ^ 1;
            if (k16 < 3) {                // issue next fragment loads first
#pragma unroll
                for (int mi = 0; mi < 2; mi++)
                    ldm_x4(af[nxt][mi], abase + mi * 16 * STRIDE + (k16 + 1) * 32);
#pragma unroll
                for (int bi = 0; bi < 4; bi++)
                    ldm_x4(bf[nxt][bi], bbase + bi * 16 * STRIDE + (k16 + 1) * 32);
            }
#pragma unroll
            for (int mi = 0; mi < 2; mi++)
#pragma unroll
                for (int ni = 0; ni < 8; ni++)
                    mma_f16(acc[mi][ni], af[cur][mi],
                            bf[cur][ni >> 1][(ni & 1) * 2], bf[cur][ni >> 1][(ni & 1) * 2 + 1]);
        }
        __syncthreads();
        if (kt + 2 < NKT) load_tile(kt + 2, s);
    }

    // ---------------- epilogue: InstanceNorm + ReLU from registers ----------
    float* sps  = (float*)smem;          // [64][8]
    float* sps2 = sps + 64 * 8;          // [64][8]

    float ps[2][2]   = {{0.f, 0.f}, {0.f, 0.f}};
    float ps2v[2][2] = {{0.f, 0.f}, {0.f, 0.f}};
#pragma unroll
    for (int mi = 0; mi < 2; mi++)
#pragma unroll
        for (int ni = 0; ni < 8; ni++) {
            float a0 = acc[mi][ni][0], a1 = acc[mi][ni][1];
            float a2 = acc[mi][ni][2], a3 = acc[mi][ni][3];
            ps[mi][0] += a0 + a1;  ps2v[mi][0] += a0 * a0 + a1 * a1;
            ps[mi][1] += a2 + a3;  ps2v[mi][1] += a2 * a2 + a3 * a3;
        }
#pragma unroll
    for (int o = 1; o <= 2; o <<= 1)
#pragma unroll
        for (int mi = 0; mi < 2; mi++)
#pragma unroll
            for (int h = 0; h < 2; h++) {
                ps[mi][h]   += __shfl_xor_sync(0xffffffffu, ps[mi][h],   o);
                ps2v[mi][h] += __shfl_xor_sync(0xffffffffu, ps2v[mi][h], o);
            }
    if (quad == 0) {
#pragma unroll
        for (int mi = 0; mi < 2; mi++)
#pragma unroll
            for (int h = 0; h < 2; h++) {
                int r = warp_m * 32 + mi * 16 + grp + h * 8;
                sps[r * 8 + warp_n]  = ps[mi][h];
                sps2[r * 8 + warp_n] = ps2v[mi][h];
            }
    }
    __syncthreads();

    const float inv_l = 1.0f / (float)LSQ;
#pragma unroll
    for (int mi = 0; mi < 2; mi++) {
#pragma unroll
        for (int h = 0; h < 2; h++) {
            const int r = warp_m * 32 + mi * 16 + grp + h * 8;
            float S = 0.f, S2 = 0.f;
#pragma unroll
            for (int w = 0; w < 8; w++) { S += sps[r * 8 + w]; S2 += sps2[r * 8 + w]; }
            const float mu = S * inv_l;
            const float var = S2 * inv_l - mu * mu;
            const float rstd = rsqrtf(var + 1e-5f);
            float* orow = out + ((size_t)b * CCH + mt * 64 + r) * LSQ;
#pragma unroll
            for (int ni = 0; ni < 8; ni++) {
                const int col = warp_n * 64 + ni * 8 + quad * 2;
                float y0 = fmaxf((acc[mi][ni][2 * h + 0] - mu) * rstd, 0.f);
                float y1 = fmaxf((acc[mi][ni][2 * h + 1] - mu) * rstd, 0.f);
                *(float2*)&orow[col] = make_float2(y0, y1);
            }
        }
    }
}

// ---------------------------------------------------------------------------
// launch
// ---------------------------------------------------------------------------
extern "C" void kernel_launch(void* const* d_in, const int* in_sizes, int n_in,
                              void* d_out, int out_size) {
    const float* x   = (const float*)d_in[0];   // [B, C, L]
    const int*   idx = (const int*)d_in[1];     // [B, L]
    const float* W   = (const float*)d_in[2];   // [C, 2C] (bias cancels under InstanceNorm)
    float* out = (float*)d_out;

    cudaFuncSetAttribute(gemm_kernel, cudaFuncAttributeMaxDynamicSharedMemorySize, GSMEM);

    prep_kernel<<<(CCH * KTOT + 255) / 256, 256>>>(W);

    dim3 cgrid(LSQ / 32, CCH / 128, BATCH);
    conv_kernel<<<cgrid, 256>>>(x);

    dim3 ggrid(CCH / 64, BATCH);     // 4 x 256 = 1024 CTAs
    gemm_kernel<<<ggrid, 512, GSMEM>>>(idx, out);
}

// round 17
// speedup vs baseline: 1.1311x; 1.0757x over previous
#include <cuda_runtime.h>
#include <cuda_fp16.h>
#include <cstdint>

#define BATCH 256
#define CCH   256
#define LSQ   512
#define TWOC  512
#define KTOT  512       // [xh ; gathered xh]

// ---------------------------------------------------------------------------
__device__ __half  g_A[CCH * KTOT];                     // 256 KB  = fp16(W)
__device__ __half  g_xh[(size_t)BATCH * LSQ * CCH];     // 67 MB [b, l, c]

// ---------------------------------------------------------------------------
__device__ __forceinline__ uint32_t s2u(const void* p) {
    uint32_t a;
    asm("{ .reg .u64 t; cvta.to.shared.u64 t, %1; cvt.u32.u64 %0, t; }" : "=r"(a) : "l"(p));
    return a;
}
__device__ __forceinline__ void cpasync16(uint32_t dst, const void* src) {
    asm volatile("cp.async.cg.shared.global [%0], [%1], 16;" :: "r"(dst), "l"(src) : "memory");
}
__device__ __forceinline__ void cpasync16z(uint32_t dst, const void* src, uint32_t sz) {
    asm volatile("cp.async.cg.shared.global [%0], [%1], 16, %2;"
                 :: "r"(dst), "l"(src), "r"(sz) : "memory");
}
__device__ __forceinline__ void cp_commit() {
    asm volatile("cp.async.commit_group;" ::: "memory");
}
__device__ __forceinline__ void cp_wait1() {
    asm volatile("cp.async.wait_group 1;" ::: "memory");
}
__device__ __forceinline__ void cp_wait0() {
    asm volatile("cp.async.wait_group 0;" ::: "memory");
}
__device__ __forceinline__ void ldm_x4(uint32_t* r, uint32_t addr) {
    asm volatile("ldmatrix.sync.aligned.m8n8.x4.shared.b16 {%0,%1,%2,%3}, [%4];"
                 : "=r"(r[0]), "=r"(r[1]), "=r"(r[2]), "=r"(r[3]) : "r"(addr));
}
__device__ __forceinline__ void mma_f16(float* c, const uint32_t* a, uint32_t b0, uint32_t b1) {
    asm volatile(
        "mma.sync.aligned.m16n8k16.row.col.f32.f16.f16.f32 "
        "{%0,%1,%2,%3}, {%4,%5,%6,%7}, {%8,%9}, {%0,%1,%2,%3};"
        : "+f"(c[0]), "+f"(c[1]), "+f"(c[2]), "+f"(c[3])
        : "r"(a[0]), "r"(a[1]), "r"(a[2]), "r"(a[3]), "r"(b0), "r"(b1));
}

// ---------------------------------------------------------------------------
// Kernel 1: A = fp16(W)
// ---------------------------------------------------------------------------
__global__ void prep_kernel(const float* __restrict__ W) {
    int i = blockIdx.x * blockDim.x + threadIdx.x;
    if (i < CCH * KTOT) g_A[i] = __float2half(W[i]);
}

// ---------------------------------------------------------------------------
// Kernel 2: transpose + convert x[b,c,l] f32 -> xh[b,l,c] fp16
// ---------------------------------------------------------------------------
__global__ __launch_bounds__(256)
void conv_kernel(const float* __restrict__ x) {
    __shared__ float tile[128][33];
    int b  = blockIdx.z;
    int l0 = blockIdx.x * 32;
    int c0 = blockIdx.y * 128;
    int lane = threadIdx.x & 31, w = threadIdx.x >> 5;

    const float* xb = x + ((size_t)b * CCH + c0) * LSQ + l0;
#pragma unroll
    for (int i = 0; i < 16; i++) {
        int c = w + i * 8;
        tile[c][lane] = xb[(size_t)c * LSQ + lane];
    }
    __syncthreads();

#pragma unroll
    for (int i = 0; i < 4; i++) {
        int l = w + i * 8;
        int c4 = lane * 4;
        __half2 h01 = __floats2half2_rn(tile[c4 + 0][l], tile[c4 + 1][l]);
        __half2 h23 = __floats2half2_rn(tile[c4 + 2][l], tile[c4 + 3][l]);
        size_t o = ((size_t)b * LSQ + l0 + l) * CCH + c0 + c4;
        *(uint2*)(g_xh + o) = make_uint2(*(uint32_t*)&h01, *(uint32_t*)&h23);
    }
}

// ---------------------------------------------------------------------------
// Kernel 3: fused GEMM (K=512, gather in B loads) + InstanceNorm + ReLU
//   CTA: M=64 x N=512, BK=64, 3-stage cp.async, lookahead-2, 1 sync/kt
//   512 threads, warps 2(m) x 8(n); smem XOR swizzle (128B rows, no padding)
// ---------------------------------------------------------------------------
#define BK      64
#define ROWB    128                      // bytes per smem row (64 fp16)
#define A_SZ    (64 * ROWB)              // 8192
#define B_SZ    (512 * ROWB)             // 65536
#define STAGE_B (A_SZ + B_SZ)            // 73728
#define NKT     (KTOT / BK)              // 8
#define SM_IDX  (3 * STAGE_B)            // 221184
#define GSMEM   (SM_IDX + LSQ * 4)       // 223232

__global__ __launch_bounds__(512, 1)
void gemm_kernel(const int* __restrict__ idx, float* __restrict__ out) {
    extern __shared__ char smem[];
    const uint32_t sb = s2u(smem);
    int* sidx = (int*)(smem + SM_IDX);

    const int tid = threadIdx.x;
    const int wid = tid >> 5;
    const int lane = tid & 31;
    const int mt = blockIdx.x;           // 0..3
    const int b  = blockIdx.y;

    const int warp_m = wid & 1;          // 32 rows
    const int warp_n = wid >> 1;         // 64 cols
    const int grp = lane >> 2, quad = lane & 3;

    const uint32_t xsw  = (uint32_t)(lane & 7) << 4;   // per-lane swizzle XOR
    const uint32_t a_row = (uint32_t)(warp_m * 32 + (lane & 15)) * ROWB;
    const uint32_t a_c0  = (uint32_t)(lane >> 4) * 16;
    const uint32_t b_row = (uint32_t)(warp_n * 64 + (lane & 7) + ((lane >> 4) << 3)) * ROWB;
    const uint32_t b_c0  = (uint32_t)((lane >> 3) & 1) * 16;

    sidx[tid] = idx[(size_t)b * LSQ + tid];

    float acc[2][8][4];
#pragma unroll
    for (int i = 0; i < 2; i++)
#pragma unroll
        for (int j = 0; j < 8; j++)
#pragma unroll
            for (int k = 0; k < 4; k++) acc[i][j][k] = 0.f;

    // cp.async coords: A row tid>>3 (0..63) chunk tid&7; B 4096 chunks / 512 thr
    const uint32_t ga_row = tid >> 3, ga_c = tid & 7;
    const uint32_t ga_dst = ga_row * ROWB + ((ga_c * 16) ^ ((ga_row & 7) << 4));

    auto load_tile = [&](int kt, int s) {
        const uint32_t base = sb + s * STAGE_B;
        {
            const void* src = g_A + (size_t)(mt * 64 + ga_row) * KTOT + kt * BK + ga_c * 8;
            cpasync16(base + ga_dst, src);
        }
        if (kt < 4) {
#pragma unroll
            for (int i = 0; i < 8; i++) {
                int t = tid + i * 512;
                uint32_t row = t >> 3, c16 = t & 7;
                const void* src = g_xh + ((size_t)b * LSQ + row) * CCH + kt * BK + c16 * 8;
                cpasync16(base + A_SZ + row * ROWB + ((c16 * 16) ^ ((row & 7) << 4)), src);
            }
        } else {
            const int kb = (kt - 4) * BK;
#pragma unroll
            for (int i = 0; i < 8; i++) {
                int t = tid + i * 512;
                uint32_t row = t >> 3, c16 = t & 7;
                int j = sidx[row];
                int jc = (j < LSQ) ? j : 0;
                uint32_t sz = (j < LSQ) ? 16u : 0u;
                const void* src = g_xh + ((size_t)b * LSQ + jc) * CCH + kb + c16 * 8;
                cpasync16z(base + A_SZ + row * ROWB + ((c16 * 16) ^ ((row & 7) << 4)), src, sz);
            }
        }
        cp_commit();
    };

    __syncthreads();                      // publish sidx
    load_tile(0, 0);
    load_tile(1, 1);

    for (int kt = 0; kt < NKT; kt++) {
        const int s = kt % 3;
        if (kt == NKT - 1) cp_wait0(); else cp_wait1();
        __syncthreads();   // loads of stage s visible; all warps past compute kt-1
        if (kt + 2 < NKT) load_tile(kt + 2, (kt + 2) % 3);   // stage from kt-1: safe

        const uint32_t abase = sb + s * STAGE_B + a_row;
        const uint32_t bbase = sb + s * STAGE_B + A_SZ + b_row;
#pragma unroll
        for (int k16 = 0; k16 < 4; k16++) {
            uint32_t af[2][4], bf[4][4];
            const uint32_t ac = (a_c0 + k16 * 32) ^ xsw;
            const uint32_t bc = (b_c0 + k16 * 32) ^ xsw;
#pragma unroll
            for (int mi = 0; mi < 2; mi++)
                ldm_x4(af[mi], abase + mi * 16 * ROWB + ac);
#pragma unroll
            for (int bi = 0; bi < 4; bi++)
                ldm_x4(bf[bi], bbase + bi * 16 * ROWB + bc);
#pragma unroll
            for (int mi = 0; mi < 2; mi++)
#pragma unroll
                for (int ni = 0; ni < 8; ni++)
                    mma_f16(acc[mi][ni], af[mi],
                            bf[ni >> 1][(ni & 1) * 2], bf[ni >> 1][(ni & 1) * 2 + 1]);
        }
    }

    // ---------------- epilogue: InstanceNorm + ReLU from registers ----------
    // stage-0 region reused for partials: last compute on stage 0 was kt=6,
    // protected by kt=7's barrier; stage 1 (kt=7) region untouched.
    float* sps  = (float*)smem;          // [64][8]
    float* sps2 = sps + 64 * 8;          // [64][8]

    float ps[2][2]   = {{0.f, 0.f}, {0.f, 0.f}};
    float ps2v[2][2] = {{0.f, 0.f}, {0.f, 0.f}};
#pragma unroll
    for (int mi = 0; mi < 2; mi++)
#pragma unroll
        for (int ni = 0; ni < 8; ni++) {
            float a0 = acc[mi][ni][0], a1 = acc[mi][ni][1];
            float a2 = acc[mi][ni][2], a3 = acc[mi][ni][3];
            ps[mi][0] += a0 + a1;  ps2v[mi][0] += a0 * a0 + a1 * a1;
            ps[mi][1] += a2 + a3;  ps2v[mi][1] += a2 * a2 + a3 * a3;
        }
#pragma unroll
    for (int o = 1; o <= 2; o <<= 1)
#pragma unroll
        for (int mi = 0; mi < 2; mi++)
#pragma unroll
            for (int h = 0; h < 2; h++) {
                ps[mi][h]   += __shfl_xor_sync(0xffffffffu, ps[mi][h],   o);
                ps2v[mi][h] += __shfl_xor_sync(0xffffffffu, ps2v[mi][h], o);
            }
    __syncthreads();                      // all warps done with mainloop smem reads
    if (quad == 0) {
#pragma unroll
        for (int mi = 0; mi < 2; mi++)
#pragma unroll
            for (int h = 0; h < 2; h++) {
                int r = warp_m * 32 + mi * 16 + grp + h * 8;
                sps[r * 8 + warp_n]  = ps[mi][h];
                sps2[r * 8 + warp_n] = ps2v[mi][h];
            }
    }
    __syncthreads();

    const float inv_l = 1.0f / (float)LSQ;
#pragma unroll
    for (int mi = 0; mi < 2; mi++) {
#pragma unroll
        for (int h = 0; h < 2; h++) {
            const int r = warp_m * 32 + mi * 16 + grp + h * 8;
            float S = 0.f, S2 = 0.f;
#pragma unroll
            for (int w = 0; w < 8; w++) { S += sps[r * 8 + w]; S2 += sps2[r * 8 + w]; }
            const float mu = S * inv_l;
            const float var = S2 * inv_l - mu * mu;
            const float rstd = rsqrtf(var + 1e-5f);
            float* orow = out + ((size_t)b * CCH + mt * 64 + r) * LSQ;
#pragma unroll
            for (int ni = 0; ni < 8; ni++) {
                const int col = warp_n * 64 + ni * 8 + quad * 2;
                float y0 = fmaxf((acc[mi][ni][2 * h + 0] - mu) * rstd, 0.f);
                float y1 = fmaxf((acc[mi][ni][2 * h + 1] - mu) * rstd, 0.f);
                *(float2*)&orow[col] = make_float2(y0, y1);
            }
        }
    }
}

// ---------------------------------------------------------------------------
// launch
// ---------------------------------------------------------------------------
extern "C" void kernel_launch(void* const* d_in, const int* in_sizes, int n_in,
                              void* d_out, int out_size) {
    const float* x   = (const float*)d_in[0];   // [B, C, L]
    const int*   idx = (const int*)d_in[1];     // [B, L]
    const float* W   = (const float*)d_in[2];   // [C, 2C] (bias cancels under InstanceNorm)
    float* out = (float*)d_out;

    cudaFuncSetAttribute(gemm_kernel, cudaFuncAttributeMaxDynamicSharedMemorySize, GSMEM);

    prep_kernel<<<(CCH * KTOT + 255) / 256, 256>>>(W);

    dim3 cgrid(LSQ / 32, CCH / 128, BATCH);
    conv_kernel<<<cgrid, 256>>>(x);

    dim3 ggrid(CCH / 64, BATCH);     // 4 x 256 = 1024 CTAs
    gemm_kernel<<<ggrid, 512, GSMEM>>>(idx, out);
}